// round 2
// baseline (speedup 1.0000x reference)
#include <cuda_runtime.h>
#include <cuda_bf16.h>
#include <cstdint>

// BahdanauAttention with size-1 attention axis:
//   softmax over length-1 axis == 1.0 -> attention_weights = ones
//   context = features (bit-exact copy). Score GEMMs are dead code.
// Pure HBM streaming: 128 MiB read + 128 MiB write.

static constexpr int Bsz = 16384;
static constexpr int Dsz = 2048;
static constexpr int CTX_VECS = (Bsz * Dsz) / 4;   // 8,388,608 float4 (2^23)
static constexpr int AW_VECS  = Bsz / 4;           // 4,096 float4

static constexpr int THREADS = 256;
static constexpr int BLOCKS  = 2048;
static constexpr int NTHREADS = THREADS * BLOCKS;          // 524,288 = 2^19
static constexpr int VECS_PER_THREAD = CTX_VECS / NTHREADS; // 16, exact

__global__ void __launch_bounds__(THREADS)
bahdanau_copy_kernel(const float4* __restrict__ features, float4* __restrict__ out) {
    int tid = blockIdx.x * THREADS + threadIdx.x;

    // Copy 16 float4 per thread, unrolled in groups of 4 independent loads
    // (MLP=4 front-batched) with exact bounds -> no compares in the loop.
    #pragma unroll
    for (int g = 0; g < VECS_PER_THREAD; g += 4) {
        int i0 = tid + (g + 0) * NTHREADS;
        int i1 = tid + (g + 1) * NTHREADS;
        int i2 = tid + (g + 2) * NTHREADS;
        int i3 = tid + (g + 3) * NTHREADS;
        float4 a0 = __ldcs(&features[i0]);
        float4 a1 = __ldcs(&features[i1]);
        float4 a2 = __ldcs(&features[i2]);
        float4 a3 = __ldcs(&features[i3]);
        __stcs(&out[i0], a0);
        __stcs(&out[i1], a1);
        __stcs(&out[i2], a2);
        __stcs(&out[i3], a3);
    }

    // Trailing ones for attention_weights: one extra store for 4096 threads.
    if (tid < AW_VECS) {
        __stcs(&out[CTX_VECS + tid], make_float4(1.f, 1.f, 1.f, 1.f));
    }
}

extern "C" void kernel_launch(void* const* d_in, const int* in_sizes, int n_in,
                              void* d_out, int out_size) {
    const float4* features = (const float4*)d_in[0];
    float4* out = (float4*)d_out;
    bahdanau_copy_kernel<<<BLOCKS, THREADS>>>(features, out);
}

// round 3
// speedup vs baseline: 1.0425x; 1.0425x over previous
#include <cuda_runtime.h>
#include <cuda_bf16.h>
#include <cstdint>

// BahdanauAttention with size-1 attention axis:
//   softmax over length-1 axis == 1.0 -> attention_weights = ones
//   context = features (bit-exact copy). Score GEMMs are dead code.
// Pure HBM streaming: 128 MiB read + 128 MiB write + 64 KiB fill.

static constexpr int Bsz = 16384;
static constexpr int Dsz = 2048;
static constexpr int CTX_VECS = (Bsz * Dsz) / 4;   // 8,388,608 float4 (2^23)
static constexpr int AW_VECS  = Bsz / 4;           // 4,096 float4

static constexpr int THREADS = 256;
static constexpr int BLOCKS  = 2048;
static constexpr int NTHREADS = THREADS * BLOCKS;           // 524,288 = 2^19
static constexpr int VECS_PER_THREAD = CTX_VECS / NTHREADS; // 16, exact

__global__ void __launch_bounds__(THREADS)
bahdanau_copy_kernel(const float4* __restrict__ features, float4* __restrict__ out) {
    int tid = blockIdx.x * THREADS + threadIdx.x;

    // 16 float4 per thread, two groups of 8 front-batched independent loads
    // (MLP=8). Default cache ops: zero-reuse stream, .cs hints measurably
    // hurt DRAM% in round 2. Exact bounds -> no compares, 32-bit indexing.
    #pragma unroll
    for (int g = 0; g < VECS_PER_THREAD; g += 8) {
        float4 a[8];
        #pragma unroll
        for (int j = 0; j < 8; j++)
            a[j] = features[tid + (g + j) * NTHREADS];
        #pragma unroll
        for (int j = 0; j < 8; j++)
            out[tid + (g + j) * NTHREADS] = a[j];
    }

    // Trailing ones for attention_weights: one extra store for 4096 threads.
    if (tid < AW_VECS) {
        out[CTX_VECS + tid] = make_float4(1.f, 1.f, 1.f, 1.f);
    }
}

extern "C" void kernel_launch(void* const* d_in, const int* in_sizes, int n_in,
                              void* d_out, int out_size) {
    const float4* features = (const float4*)d_in[0];
    float4* out = (float4*)d_out;
    bahdanau_copy_kernel<<<BLOCKS, THREADS>>>(features, out);
}

// round 4
// speedup vs baseline: 1.0499x; 1.0070x over previous
#include <cuda_runtime.h>
#include <cuda_bf16.h>
#include <cstdint>

// BahdanauAttention with size-1 attention axis:
//   softmax over length-1 axis == 1.0 -> attention_weights = ones
//   context = features (bit-exact copy). Score GEMMs are dead code.
// Pure HBM streaming copy: 128 MiB read + 128 MiB write + 64 KiB fill.
// Single-wave grid: 1024 blocks (<= 8 resident blocks/SM on 148 SMs),
// so every CTA is resident at once -> no wave-transition tail.

static constexpr int Bsz = 16384;
static constexpr int Dsz = 2048;
static constexpr int CTX_VECS = (Bsz * Dsz) / 4;   // 8,388,608 float4 (2^23)
static constexpr int AW_VECS  = Bsz / 4;           // 4,096 float4

static constexpr int THREADS = 256;
static constexpr int BLOCKS  = 1024;
static constexpr int NTHREADS = THREADS * BLOCKS;           // 262,144 = 2^18
static constexpr int VECS_PER_THREAD = CTX_VECS / NTHREADS; // 32, exact

__global__ void __launch_bounds__(THREADS)
bahdanau_copy_kernel(const float4* __restrict__ features, float4* __restrict__ out) {
    int tid = blockIdx.x * THREADS + threadIdx.x;

    // 32 float4 per thread, four groups of 8 front-batched independent loads
    // (MLP=8; proven best in rounds 2->3). Exact bounds, 32-bit indexing.
    #pragma unroll
    for (int g = 0; g < VECS_PER_THREAD; g += 8) {
        float4 a[8];
        #pragma unroll
        for (int j = 0; j < 8; j++)
            a[j] = features[tid + (g + j) * NTHREADS];
        #pragma unroll
        for (int j = 0; j < 8; j++)
            out[tid + (g + j) * NTHREADS] = a[j];
    }

    // Trailing ones for attention_weights: one extra store for 4096 threads.
    if (tid < AW_VECS) {
        out[CTX_VECS + tid] = make_float4(1.f, 1.f, 1.f, 1.f);
    }
}

extern "C" void kernel_launch(void* const* d_in, const int* in_sizes, int n_in,
                              void* d_out, int out_size) {
    const float4* features = (const float4*)d_in[0];
    float4* out = (float4*)d_out;
    bahdanau_copy_kernel<<<BLOCKS, THREADS>>>(features, out);
}

// round 5
// speedup vs baseline: 1.0603x; 1.0099x over previous
#include <cuda_runtime.h>
#include <cuda_bf16.h>
#include <cstdint>

// BahdanauAttention with size-1 attention axis:
//   softmax over length-1 axis == 1.0 -> attention_weights = ones
//   context = features (bit-exact copy). Score GEMMs are dead code.
// Pure HBM streaming copy: 128 MiB read + 128 MiB write + 64 KiB fill.
//
// Round-4 lesson: exact single-wave grids load-balance WORSE than
// fine-grained oversubscription. Config: 4096 blocks x 256 thr x 8 vec
// -> one MLP=8 front-batched group per thread, minimal serial chain,
// ~28 blocks/SM for smooth self-balancing.

static constexpr int Bsz = 16384;
static constexpr int Dsz = 2048;
static constexpr int CTX_VECS = (Bsz * Dsz) / 4;   // 8,388,608 float4 (2^23)
static constexpr int AW_VECS  = Bsz / 4;           // 4,096 float4

static constexpr int THREADS = 256;
static constexpr int BLOCKS  = 4096;
static constexpr int NTHREADS = THREADS * BLOCKS;  // 1,048,576 = 2^20
// CTX_VECS / NTHREADS == 8, exact.

__global__ void __launch_bounds__(THREADS)
bahdanau_copy_kernel(const float4* __restrict__ features, float4* __restrict__ out) {
    int tid = blockIdx.x * THREADS + threadIdx.x;

    // Exactly 8 float4 per thread, all loads front-batched (MLP=8).
    float4 a[8];
    #pragma unroll
    for (int j = 0; j < 8; j++)
        a[j] = features[tid + j * NTHREADS];
    #pragma unroll
    for (int j = 0; j < 8; j++)
        out[tid + j * NTHREADS] = a[j];

    // Trailing ones for attention_weights: one extra store for 4096 threads.
    if (tid < AW_VECS) {
        out[CTX_VECS + tid] = make_float4(1.f, 1.f, 1.f, 1.f);
    }
}

extern "C" void kernel_launch(void* const* d_in, const int* in_sizes, int n_in,
                              void* d_out, int out_size) {
    const float4* features = (const float4*)d_in[0];
    float4* out = (float4*)d_out;
    bahdanau_copy_kernel<<<BLOCKS, THREADS>>>(features, out);
}